// round 4
// baseline (speedup 1.0000x reference)
#include <cuda_runtime.h>
#include <cuda_bf16.h>
#include <cstdint>

// ---------------- problem constants ----------------
#define BROWS   65536
#define DDIM    1024
#define NCOLS   128      // 120 real columns padded to 128
#define KC      64       // K elems staged per chunk
#define NCHUNK  (DDIM / KC)   // 16
#define TILE_M  128
#define APAD    72       // smem row pitch (bf16 elems) for A/B stage: conflict-free frags
#define OPAD    130      // smem row pitch (floats) for output tile: even -> aligned float2

// packed weights: [NCOLS][DDIM] K-major bf16 (256 KB static device array — no alloc)
__device__ __align__(16) __nv_bfloat16 g_Wpack[NCOLS * DDIM];

// ---------------- weight pack kernel ----------------
// col j:  j<100: expert (e=j/10, u=j%10) ; 100<=j<120: gate (t=(j-100)/10, e=(j-100)%10) ; else 0
__global__ void pack_weights_kernel(const float* __restrict__ expert_w,
                                    const float* __restrict__ gate_w) {
    int j = blockIdx.x;                       // 0..127
    for (int d = threadIdx.x; d < DDIM; d += blockDim.x) {
        float v = 0.0f;
        if (j < 100) {
            int e = j / 10, u = j % 10;
            v = expert_w[((size_t)e * DDIM + d) * 10 + u];
        } else if (j < 120) {
            int idx = j - 100;
            int t = idx / 10, e = idx % 10;
            v = gate_w[((size_t)t * DDIM + d) * 10 + e];
        }
        g_Wpack[(size_t)j * DDIM + d] = __float2bfloat16(v);
    }
}

// ---------------- fused MMoE main kernel ----------------
// dynamic smem union:
//   stage:  A [128][APAD] bf16 @0 (18432 B), B [128][APAD] bf16 @18432 (18432 B)
//   outS:   [128][OPAD] float @0 (66560 B)   <- used only after main loop
#define SMEM_BYTES (TILE_M * OPAD * 4)   // 66560

extern "C" __global__ void __launch_bounds__(256, 2)
mmoe_main_kernel(const float* __restrict__ x,
                 const float* __restrict__ expert_b,   // [10,10] (E,U) flat [e*10+u]
                 const float* __restrict__ gate_b,     // [2,10]
                 const float* __restrict__ ctr_w,      // [10]
                 const float* __restrict__ ctr_b,      // [1]
                 const float* __restrict__ cvr_w,      // [10]
                 const float* __restrict__ cvr_b,      // [1]
                 float* __restrict__ out) {            // [2*B] = [ctr | cvr]
    extern __shared__ char smem[];
    __nv_bfloat16* Asm = reinterpret_cast<__nv_bfloat16*>(smem);
    __nv_bfloat16* Bsm = reinterpret_cast<__nv_bfloat16*>(smem + TILE_M * APAD * 2);
    float*         outS = reinterpret_cast<float*>(smem);

    const int tid  = threadIdx.x;
    const int wid  = tid >> 5;
    const int lane = tid & 31;
    const int gid  = lane >> 2;   // 0..7
    const int tig  = lane & 3;    // 0..3
    const int warp_m = (wid & 3) * 32;   // 4 warps along M
    const int warp_n = (wid >> 2) * 64;  // 2 warps along N
    const int row0 = blockIdx.x * TILE_M;

    float acc[2][8][4];
    #pragma unroll
    for (int mt = 0; mt < 2; ++mt)
        #pragma unroll
        for (int nt = 0; nt < 8; ++nt)
            #pragma unroll
            for (int i = 0; i < 4; ++i) acc[mt][nt][i] = 0.0f;

    for (int c = 0; c < NCHUNK; ++c) {
        const int k0 = c * KC;
        __syncthreads();   // previous chunk's MMAs done reading the stage

        // --- stage A: x[row0..+127][k0..+63] fp32 -> bf16 ---
        #pragma unroll
        for (int it = 0; it < 8; ++it) {
            int f = tid + it * 256;           // float4 index over 128x64 tile
            int row = f >> 4, c4 = f & 15;
            const float4 v = *reinterpret_cast<const float4*>(
                x + (size_t)(row0 + row) * DDIM + k0 + c4 * 4);
            *reinterpret_cast<__nv_bfloat162*>(Asm + row * APAD + c4 * 4) =
                __floats2bfloat162_rn(v.x, v.y);
            *reinterpret_cast<__nv_bfloat162*>(Asm + row * APAD + c4 * 4 + 2) =
                __floats2bfloat162_rn(v.z, v.w);
        }
        // --- stage B: W[0..127][k0..+63] bf16 (16B copies) ---
        #pragma unroll
        for (int it = 0; it < 4; ++it) {
            int f = tid + it * 256;           // uint4 index over 128x64 bf16 tile
            int row = f >> 3, c8 = f & 7;
            const uint4 v = *reinterpret_cast<const uint4*>(
                g_Wpack + (size_t)row * DDIM + k0 + c8 * 8);
            *reinterpret_cast<uint4*>(Bsm + row * APAD + c8 * 8) = v;
        }
        __syncthreads();

        // --- compute: 4 k-tiles of 16 ---
        #pragma unroll
        for (int kt = 0; kt < 4; ++kt) {
            const int colk = kt * 16 + tig * 2;
            uint32_t afrag[2][4];
            #pragma unroll
            for (int mt = 0; mt < 2; ++mt) {
                const int mb = warp_m + mt * 16;
                afrag[mt][0] = *reinterpret_cast<const uint32_t*>(Asm + (mb + gid)     * APAD + colk);
                afrag[mt][1] = *reinterpret_cast<const uint32_t*>(Asm + (mb + gid + 8) * APAD + colk);
                afrag[mt][2] = *reinterpret_cast<const uint32_t*>(Asm + (mb + gid)     * APAD + colk + 8);
                afrag[mt][3] = *reinterpret_cast<const uint32_t*>(Asm + (mb + gid + 8) * APAD + colk + 8);
            }
            #pragma unroll
            for (int nt = 0; nt < 8; ++nt) {
                const int n = warp_n + nt * 8 + gid;
                const uint32_t b0 = *reinterpret_cast<const uint32_t*>(Bsm + n * APAD + colk);
                const uint32_t b1 = *reinterpret_cast<const uint32_t*>(Bsm + n * APAD + colk + 8);
                #pragma unroll
                for (int mt = 0; mt < 2; ++mt) {
                    asm volatile(
                        "mma.sync.aligned.m16n8k16.row.col.f32.bf16.bf16.f32 "
                        "{%0,%1,%2,%3}, {%4,%5,%6,%7}, {%8,%9}, {%0,%1,%2,%3};"
                        : "+f"(acc[mt][nt][0]), "+f"(acc[mt][nt][1]),
                          "+f"(acc[mt][nt][2]), "+f"(acc[mt][nt][3])
                        : "r"(afrag[mt][0]), "r"(afrag[mt][1]),
                          "r"(afrag[mt][2]), "r"(afrag[mt][3]),
                          "r"(b0), "r"(b1));
                }
            }
        }
    }
    __syncthreads();   // all MMAs done; stage buffers dead -> reuse smem as outS

    // --- scatter accumulators to fp32 out tile ---
    #pragma unroll
    for (int mt = 0; mt < 2; ++mt) {
        #pragma unroll
        for (int nt = 0; nt < 8; ++nt) {
            const int r = warp_m + mt * 16 + gid;
            const int col = warp_n + nt * 8 + tig * 2;
            *reinterpret_cast<float2*>(outS + r * OPAD + col) =
                make_float2(acc[mt][nt][0], acc[mt][nt][1]);
            *reinterpret_cast<float2*>(outS + (r + 8) * OPAD + col) =
                make_float2(acc[mt][nt][2], acc[mt][nt][3]);
        }
    }
    __syncthreads();

    // --- per-row epilogue: softmax gates, expert mix, sigmoid heads ---
    if (tid < TILE_M) {
        const float* rowv = outS + tid * OPAD;

        float g[2][10];
        #pragma unroll
        for (int t = 0; t < 2; ++t) {
            float s = 0.0f;
            #pragma unroll
            for (int e = 0; e < 10; ++e) {
                float l = rowv[100 + t * 10 + e] + gate_b[t * 10 + e];
                float ex = expf(l);
                g[t][e] = ex; s += ex;
            }
            float inv = 1.0f / s;
            #pragma unroll
            for (int e = 0; e < 10; ++e) g[t][e] *= inv;
        }

        float ti0[10], ti1[10];
        #pragma unroll
        for (int u = 0; u < 10; ++u) { ti0[u] = 0.0f; ti1[u] = 0.0f; }
        #pragma unroll
        for (int e = 0; e < 10; ++e) {
            const float g0 = g[0][e], g1 = g[1][e];
            #pragma unroll
            for (int u = 0; u < 10; ++u) {
                const int j = e * 10 + u;
                float v = fmaxf(rowv[j] + expert_b[j], 0.0f);
                ti0[u] += v * g0;
                ti1[u] += v * g1;
            }
        }

        float zc = ctr_b[0], zv = cvr_b[0];
        #pragma unroll
        for (int u = 0; u < 10; ++u) {
            zc += ti0[u] * ctr_w[u];
            zv += ti1[u] * cvr_w[u];
        }
        const int gr = row0 + tid;
        out[gr]         = 1.0f / (1.0f + expf(-zc));
        out[BROWS + gr] = 1.0f / (1.0f + expf(-zv));
    }
}

// ---------------- launch ----------------
extern "C" void kernel_launch(void* const* d_in, const int* in_sizes, int n_in,
                              void* d_out, int out_size) {
    const float* x        = (const float*)d_in[0];
    // d_in[1] show_index, d_in[2] st : unused by the reference outputs
    const float* expert_w = (const float*)d_in[3];
    const float* expert_b = (const float*)d_in[4];
    const float* gate_w   = (const float*)d_in[5];
    const float* gate_b   = (const float*)d_in[6];
    const float* ctr_w    = (const float*)d_in[7];
    const float* ctr_b    = (const float*)d_in[8];
    const float* cvr_w    = (const float*)d_in[9];
    const float* cvr_b    = (const float*)d_in[10];
    float* out = (float*)d_out;

    cudaFuncSetAttribute(mmoe_main_kernel,
                         cudaFuncAttributeMaxDynamicSharedMemorySize, SMEM_BYTES);

    pack_weights_kernel<<<NCOLS, 256>>>(expert_w, gate_w);
    mmoe_main_kernel<<<BROWS / TILE_M, 256, SMEM_BYTES>>>(
        x, expert_b, gate_b, ctr_w, ctr_b, cvr_w, cvr_b, out);
}

// round 5
// speedup vs baseline: 1.2874x; 1.2874x over previous
#include <cuda_runtime.h>
#include <cuda_bf16.h>
#include <cstdint>

// ---------------- problem constants ----------------
#define BROWS   65536
#define DDIM    1024
#define NCOLS   128      // 120 real columns padded to 128
#define KC      64       // K elems staged per chunk
#define NCHUNK  (DDIM / KC)   // 16
#define TILE_M  128
#define APAD    72       // smem row pitch (bf16 elems): conflict-free frag LDS
#define OPAD    130      // out-tile row pitch (floats)

#define ABYTES  (TILE_M * APAD * 2)     // 18432 per A buffer
#define BOFF    (2 * ABYTES)            // 36864
#define SMEM_BYTES (4 * ABYTES)         // 73728 (>= out tile 66560)

// packed weights: [NCOLS][DDIM] K-major bf16 (256 KB static device array — no alloc)
__device__ __align__(16) __nv_bfloat16 g_Wpack[NCOLS * DDIM];

__device__ __forceinline__ uint32_t smem_u32(const void* p) {
    uint32_t a;
    asm("{ .reg .u64 t; cvta.to.shared.u64 t, %1; cvt.u32.u64 %0, t; }" : "=r"(a) : "l"(p));
    return a;
}
#define CP_ASYNC16(dst_u32, src_ptr) \
    asm volatile("cp.async.cg.shared.global [%0], [%1], 16;" :: "r"(dst_u32), "l"(src_ptr) : "memory")
#define CP_COMMIT() asm volatile("cp.async.commit_group;" ::: "memory")
#define CP_WAIT0()  asm volatile("cp.async.wait_group 0;" ::: "memory")

// ---------------- weight pack kernel ----------------
__global__ void pack_weights_kernel(const float* __restrict__ expert_w,
                                    const float* __restrict__ gate_w) {
    int j = blockIdx.x;                       // 0..127
    for (int d = threadIdx.x; d < DDIM; d += blockDim.x) {
        float v = 0.0f;
        if (j < 100) {
            int e = j / 10, u = j % 10;
            v = expert_w[((size_t)e * DDIM + d) * 10 + u];
        } else if (j < 120) {
            int idx = j - 100;
            int t = idx / 10, e = idx % 10;
            v = gate_w[((size_t)t * DDIM + d) * 10 + e];
        }
        g_Wpack[(size_t)j * DDIM + d] = __float2bfloat16(v);
    }
}

// ---------------- fused MMoE main kernel ----------------
extern "C" __global__ void __launch_bounds__(256, 2)
mmoe_main_kernel(const float* __restrict__ x,
                 const float* __restrict__ expert_b,   // [10,10]
                 const float* __restrict__ gate_b,     // [2,10]
                 const float* __restrict__ ctr_w,      // [10]
                 const float* __restrict__ ctr_b,      // [1]
                 const float* __restrict__ cvr_w,      // [10]
                 const float* __restrict__ cvr_b,      // [1]
                 float* __restrict__ out) {            // [2*B] = [ctr | cvr]
    extern __shared__ char smem[];
    const uint32_t smem_base = smem_u32(smem);
    float* outS = reinterpret_cast<float*>(smem);

    const int tid  = threadIdx.x;
    const int wid  = tid >> 5;
    const int lane = tid & 31;
    const int gid  = lane >> 2;   // 0..7
    const int tig  = lane & 3;    // 0..3
    const int warp_m = (wid & 3) * 32;   // 4 warps along M
    const int warp_n = (wid >> 2) * 64;  // 2 warps along N
    const int row0 = blockIdx.x * TILE_M;

    // load-mapping ids
    const int rbase = tid >> 4;          // A: row base (0..15), c4 = col float4
    const int c4    = tid & 15;
    const int brb   = tid >> 3;          // B: row base (0..31), c8 = col uint4
    const int c8    = tid & 7;

    float acc[2][8][4];
    #pragma unroll
    for (int mt = 0; mt < 2; ++mt)
        #pragma unroll
        for (int nt = 0; nt < 8; ++nt)
            #pragma unroll
            for (int i = 0; i < 4; ++i) acc[mt][nt][i] = 0.0f;

    // ---- prologue: prefetch chunk 0 ----
    float4 av[8];
    #pragma unroll
    for (int it = 0; it < 8; ++it)
        av[it] = *reinterpret_cast<const float4*>(
            x + (size_t)(row0 + rbase + it * 16) * DDIM + c4 * 4);
    {
        const uint32_t bb = smem_base + BOFF;         // bbuf[0]
        #pragma unroll
        for (int it = 0; it < 4; ++it)
            CP_ASYNC16(bb + (uint32_t)((brb + it * 32) * APAD + c8 * 8) * 2,
                       g_Wpack + (size_t)(brb + it * 32) * DDIM + c8 * 8);
        CP_COMMIT();
    }

    for (int c = 0; c < NCHUNK; ++c) {
        __nv_bfloat16* Ab = reinterpret_cast<__nv_bfloat16*>(smem + (c & 1) * ABYTES);
        __nv_bfloat16* Bb = reinterpret_cast<__nv_bfloat16*>(smem + BOFF + (c & 1) * ABYTES);

        // ---- STS: convert prefetched A regs -> abuf[c&1] (8B stores, conflict-free) ----
        #pragma unroll
        for (int it = 0; it < 8; ++it) {
            __nv_bfloat162 lo = __floats2bfloat162_rn(av[it].x, av[it].y);
            __nv_bfloat162 hi = __floats2bfloat162_rn(av[it].z, av[it].w);
            uint2 pk;
            pk.x = *reinterpret_cast<uint32_t*>(&lo);
            pk.y = *reinterpret_cast<uint32_t*>(&hi);
            *reinterpret_cast<uint2*>(Ab + (rbase + it * 16) * APAD + c4 * 4) = pk;
        }

        // ---- prefetch A chunk c+1 into regs (latency hidden by MMAs below) ----
        if (c + 1 < NCHUNK) {
            const int k0n = (c + 1) * KC;
            #pragma unroll
            for (int it = 0; it < 8; ++it)
                av[it] = *reinterpret_cast<const float4*>(
                    x + (size_t)(row0 + rbase + it * 16) * DDIM + k0n + c4 * 4);
        }

        CP_WAIT0();          // B(c) copies (issued last iter, overlapped MMA(c-1)) done
        __syncthreads();     // all warps: A(c)/B(c) staged; prev MMAs retired

        // ---- issue B chunk c+1 (safe: all warps past MMA(c-1), buffer free) ----
        if (c + 1 < NCHUNK) {
            const int k0n = (c + 1) * KC;
            const uint32_t bb = smem_base + BOFF + ((c + 1) & 1) * ABYTES;
            #pragma unroll
            for (int it = 0; it < 4; ++it)
                CP_ASYNC16(bb + (uint32_t)((brb + it * 32) * APAD + c8 * 8) * 2,
                           g_Wpack + (size_t)(brb + it * 32) * DDIM + k0n + c8 * 8);
            CP_COMMIT();
        }

        // ---- compute: 4 k-tiles of 16 ----
        #pragma unroll
        for (int kt = 0; kt < 4; ++kt) {
            const int colk = kt * 16 + tig * 2;
            uint32_t afrag[2][4];
            #pragma unroll
            for (int mt = 0; mt < 2; ++mt) {
                const int mb = warp_m + mt * 16;
                afrag[mt][0] = *reinterpret_cast<const uint32_t*>(Ab + (mb + gid)     * APAD + colk);
                afrag[mt][1] = *reinterpret_cast<const uint32_t*>(Ab + (mb + gid + 8) * APAD + colk);
                afrag[mt][2] = *reinterpret_cast<const uint32_t*>(Ab + (mb + gid)     * APAD + colk + 8);
                afrag[mt][3] = *reinterpret_cast<const uint32_t*>(Ab + (mb + gid + 8) * APAD + colk + 8);
            }
            #pragma unroll
            for (int nt = 0; nt < 8; ++nt) {
                const int n = warp_n + nt * 8 + gid;
                const uint32_t b0 = *reinterpret_cast<const uint32_t*>(Bb + n * APAD + colk);
                const uint32_t b1 = *reinterpret_cast<const uint32_t*>(Bb + n * APAD + colk + 8);
                #pragma unroll
                for (int mt = 0; mt < 2; ++mt) {
                    asm volatile(
                        "mma.sync.aligned.m16n8k16.row.col.f32.bf16.bf16.f32 "
                        "{%0,%1,%2,%3}, {%4,%5,%6,%7}, {%8,%9}, {%0,%1,%2,%3};"
                        : "+f"(acc[mt][nt][0]), "+f"(acc[mt][nt][1]),
                          "+f"(acc[mt][nt][2]), "+f"(acc[mt][nt][3])
                        : "r"(afrag[mt][0]), "r"(afrag[mt][1]),
                          "r"(afrag[mt][2]), "r"(afrag[mt][3]),
                          "r"(b0), "r"(b1));
                }
            }
        }
    }
    __syncthreads();   // MMAs done; stage buffers dead -> reuse smem as outS

    // --- scatter accumulators to fp32 out tile ---
    #pragma unroll
    for (int mt = 0; mt < 2; ++mt) {
        #pragma unroll
        for (int nt = 0; nt < 8; ++nt) {
            const int r = warp_m + mt * 16 + gid;
            const int col = warp_n + nt * 8 + tig * 2;
            *reinterpret_cast<float2*>(outS + r * OPAD + col) =
                make_float2(acc[mt][nt][0], acc[mt][nt][1]);
            *reinterpret_cast<float2*>(outS + (r + 8) * OPAD + col) =
                make_float2(acc[mt][nt][2], acc[mt][nt][3]);
        }
    }
    __syncthreads();

    // --- per-row epilogue: softmax gates, expert mix, sigmoid heads ---
    if (tid < TILE_M) {
        const float* rowv = outS + tid * OPAD;

        float g[2][10];
        #pragma unroll
        for (int t = 0; t < 2; ++t) {
            float s = 0.0f;
            #pragma unroll
            for (int e = 0; e < 10; ++e) {
                float l = rowv[100 + t * 10 + e] + gate_b[t * 10 + e];
                float ex = expf(l);
                g[t][e] = ex; s += ex;
            }
            float inv = 1.0f / s;
            #pragma unroll
            for (int e = 0; e < 10; ++e) g[t][e] *= inv;
        }

        float ti0[10], ti1[10];
        #pragma unroll
        for (int u = 0; u < 10; ++u) { ti0[u] = 0.0f; ti1[u] = 0.0f; }
        #pragma unroll
        for (int e = 0; e < 10; ++e) {
            const float g0 = g[0][e], g1 = g[1][e];
            #pragma unroll
            for (int u = 0; u < 10; ++u) {
                const int j = e * 10 + u;
                float v = fmaxf(rowv[j] + expert_b[j], 0.0f);
                ti0[u] += v * g0;
                ti1[u] += v * g1;
            }
        }

        float zc = ctr_b[0], zv = cvr_b[0];
        #pragma unroll
        for (int u = 0; u < 10; ++u) {
            zc += ti0[u] * ctr_w[u];
            zv += ti1[u] * cvr_w[u];
        }
        const int gr = row0 + tid;
        out[gr]         = 1.0f / (1.0f + expf(-zc));
        out[BROWS + gr] = 1.0f / (1.0f + expf(-zv));
    }
}

// ---------------- launch ----------------
extern "C" void kernel_launch(void* const* d_in, const int* in_sizes, int n_in,
                              void* d_out, int out_size) {
    const float* x        = (const float*)d_in[0];
    const float* expert_w = (const float*)d_in[3];
    const float* expert_b = (const float*)d_in[4];
    const float* gate_w   = (const float*)d_in[5];
    const float* gate_b   = (const float*)d_in[6];
    const float* ctr_w    = (const float*)d_in[7];
    const float* ctr_b    = (const float*)d_in[8];
    const float* cvr_w    = (const float*)d_in[9];
    const float* cvr_b    = (const float*)d_in[10];
    float* out = (float*)d_out;

    cudaFuncSetAttribute(mmoe_main_kernel,
                         cudaFuncAttributeMaxDynamicSharedMemorySize, SMEM_BYTES);

    pack_weights_kernel<<<NCOLS, 256>>>(expert_w, gate_w);
    mmoe_main_kernel<<<BROWS / TILE_M, 256, SMEM_BYTES>>>(
        x, expert_b, gate_b, ctr_w, ctr_b, cvr_w, cvr_b, out);
}